// round 1
// baseline (speedup 1.0000x reference)
#include <cuda_runtime.h>
#include <cstddef>

#define NB   2
#define NN   3072
#define CC   512
#define MM   (NB * NN)      // 6144 rows total
#define HH   8
#define DD   64

// Scratch (no allocation allowed in kernel_launch) — ~50 MB of __device__ globals.
__device__ float g_q[MM * CC];
__device__ float g_k[MM * CC];
__device__ float g_v[MM * CC];
__device__ float g_att[MM * CC];

// ---------------------------------------------------------------------------
// C[M,N] = A[M,K] @ B[N,K]^T (+ bias[N])      (both operands K-contiguous)
// 64x64 tile, BK=16, 256 threads, 4x4 micro-tile per thread.
// ---------------------------------------------------------------------------
__global__ void gemm_nt(const float* __restrict__ A,
                        const float* __restrict__ Bm,
                        const float* __restrict__ bias,
                        float* __restrict__ C,
                        int M, int N, int K)
{
    __shared__ float As[16][65];
    __shared__ float Bs[16][65];

    const int bm = blockIdx.y * 64;
    const int bn = blockIdx.x * 64;
    const int tid = threadIdx.x;
    const int ty = tid >> 4;          // 0..15
    const int tx = tid & 15;          // 0..15
    const int lr = tid >> 2;          // 0..63  (load row)
    const int lc = (tid & 3) * 4;     // 0,4,8,12 (load k-offset)

    float acc[4][4] = {};

    for (int k0 = 0; k0 < K; k0 += 16) {
        float4 av = *reinterpret_cast<const float4*>(&A[(size_t)(bm + lr) * K + k0 + lc]);
        float4 bv = *reinterpret_cast<const float4*>(&Bm[(size_t)(bn + lr) * K + k0 + lc]);
        As[lc + 0][lr] = av.x; As[lc + 1][lr] = av.y;
        As[lc + 2][lr] = av.z; As[lc + 3][lr] = av.w;
        Bs[lc + 0][lr] = bv.x; Bs[lc + 1][lr] = bv.y;
        Bs[lc + 2][lr] = bv.z; Bs[lc + 3][lr] = bv.w;
        __syncthreads();

        #pragma unroll
        for (int kk = 0; kk < 16; kk++) {
            float a[4], b[4];
            #pragma unroll
            for (int r = 0; r < 4; r++) a[r] = As[kk][ty + 16 * r];
            #pragma unroll
            for (int c = 0; c < 4; c++) b[c] = Bs[kk][tx + 16 * c];
            #pragma unroll
            for (int r = 0; r < 4; r++)
                #pragma unroll
                for (int c = 0; c < 4; c++)
                    acc[r][c] += a[r] * b[c];
        }
        __syncthreads();
    }

    #pragma unroll
    for (int r = 0; r < 4; r++) {
        const int row = bm + ty + 16 * r;
        #pragma unroll
        for (int c = 0; c < 4; c++) {
            const int col = bn + tx + 16 * c;
            float val = acc[r][c];
            if (bias) val += bias[col];
            C[(size_t)row * N + col] = val;
        }
    }
}

// ---------------------------------------------------------------------------
// Sparse triplane attention: each query n has exactly 64 allowed keys,
// computable in closed form. One block per (b, n); warp h handles head h.
// ---------------------------------------------------------------------------
__global__ void attn_kernel(const float* __restrict__ q,
                            const float* __restrict__ k,
                            const float* __restrict__ v,
                            float* __restrict__ o)
{
    __shared__ float sc[HH][64];

    const int bn   = blockIdx.x;          // 0..6143
    const int b    = bn / NN;
    const int n    = bn % NN;
    const int h    = threadIdx.x >> 5;
    const int lane = threadIdx.x & 31;

    const int p   = n >> 10;
    const int rem = n & 1023;
    const int i   = rem >> 5;
    const int j   = rem & 31;

    int base0, st0, base1, st1;
    if (p == 0)      { base0 = 1024 + i * 32; st0 = 1;  base1 = 2048 + j * 32; st1 = 1;  }
    else if (p == 1) { base0 = i * 32;        st0 = 1;  base1 = 2048 + j;      st1 = 32; }
    else             { base0 = i;             st0 = 32; base1 = 1024 + j;      st1 = 32; }

    const size_t rowbase = (size_t)b * NN * CC;
    const float* qrow = q + rowbase + (size_t)n * CC + h * DD;
    const float q0 = qrow[lane];
    const float q1 = qrow[lane + 32];

    // ---- scores (warp-cooperative per key, fully coalesced 256B reads) ----
    for (int t = 0; t < 64; t++) {
        const int key = (t < 32) ? (base0 + t * st0) : (base1 + (t - 32) * st1);
        const float* krow = k + rowbase + (size_t)key * CC + h * DD;
        float pa = q0 * krow[lane] + q1 * krow[lane + 32];
        #pragma unroll
        for (int off = 16; off; off >>= 1)
            pa += __shfl_xor_sync(0xffffffffu, pa, off);
        if (lane == 0) sc[h][t] = pa * 0.125f;   // scale = D^-0.5
    }
    __syncwarp();

    // ---- softmax over the 64 allowed keys ----
    float s0 = sc[h][lane], s1 = sc[h][lane + 32];
    float m = fmaxf(s0, s1);
    #pragma unroll
    for (int off = 16; off; off >>= 1)
        m = fmaxf(m, __shfl_xor_sync(0xffffffffu, m, off));
    float e0 = __expf(s0 - m), e1 = __expf(s1 - m);
    float sum = e0 + e1;
    #pragma unroll
    for (int off = 16; off; off >>= 1)
        sum += __shfl_xor_sync(0xffffffffu, sum, off);
    const float inv = 1.0f / sum;
    sc[h][lane]      = e0 * inv;
    sc[h][lane + 32] = e1 * inv;
    __syncwarp();

    // ---- weighted sum of V ----
    float a0 = 0.f, a1 = 0.f;
    for (int t = 0; t < 64; t++) {
        const int key = (t < 32) ? (base0 + t * st0) : (base1 + (t - 32) * st1);
        const float* vrow = v + rowbase + (size_t)key * CC + h * DD;
        const float pt = sc[h][t];
        a0 += pt * vrow[lane];
        a1 += pt * vrow[lane + 32];
    }

    float* orow = o + rowbase + (size_t)n * CC + h * DD;
    orow[lane]      = a0;
    orow[lane + 32] = a1;
}

// ---------------------------------------------------------------------------
extern "C" void kernel_launch(void* const* d_in, const int* in_sizes, int n_in,
                              void* d_out, int out_size)
{
    const float* x  = (const float*)d_in[0];
    const float* Wq = (const float*)d_in[1];
    const float* Wk = (const float*)d_in[2];
    const float* Wv = (const float*)d_in[3];
    const float* Wp = (const float*)d_in[4];
    const float* bp = (const float*)d_in[5];
    float* out = (float*)d_out;

    float *q, *k, *v, *att;
    cudaGetSymbolAddress((void**)&q,   g_q);
    cudaGetSymbolAddress((void**)&k,   g_k);
    cudaGetSymbolAddress((void**)&v,   g_v);
    cudaGetSymbolAddress((void**)&att, g_att);

    dim3 ggrid(CC / 64, MM / 64);   // (8, 96)
    gemm_nt<<<ggrid, 256>>>(x, Wq, nullptr, q, MM, CC, CC);
    gemm_nt<<<ggrid, 256>>>(x, Wk, nullptr, k, MM, CC, CC);
    gemm_nt<<<ggrid, 256>>>(x, Wv, nullptr, v, MM, CC, CC);

    attn_kernel<<<MM, HH * 32>>>(q, k, v, att);

    gemm_nt<<<ggrid, 256>>>(att, Wp, bp, out, MM, CC, CC);
}

// round 5
// speedup vs baseline: 1.7897x; 1.7897x over previous
#include <cuda_runtime.h>
#include <cuda_bf16.h>
#include <cstdint>
#include <cstddef>

#define NB   2
#define NN   3072
#define CC   512
#define MM   (NB * NN)      // 6144
#define HH   8
#define DD   64
#define KK   1536           // split-K: A=[hi|lo|hi], B=[hi|hi|lo]
#define NQKV 1536

// ---------------------------------------------------------------------------
// Device scratch (no allocations allowed)
// ---------------------------------------------------------------------------
__device__ __align__(1024) __nv_bfloat16 g_A[(size_t)MM * KK];      // split activations
__device__ __align__(1024) __nv_bfloat16 g_Bqkv[(size_t)NQKV * KK]; // [Wq;Wk;Wv] split
__device__ __align__(1024) __nv_bfloat16 g_Bout[(size_t)CC * KK];   // Wp split
__device__ __align__(16)   float g_qkv[(size_t)MM * NQKV];          // q|k|v fp32
__device__ __align__(16)   float g_att[(size_t)MM * CC];            // attention out fp32

// ---------------------------------------------------------------------------
// helpers
// ---------------------------------------------------------------------------
__device__ __forceinline__ uint32_t smem_u32(const void* p) {
    uint32_t a;
    asm("{ .reg .u64 t; cvta.to.shared.u64 t, %1; cvt.u32.u64 %0, t; }" : "=r"(a) : "l"(p));
    return a;
}

#define CP16(dst_u32, src_ptr) \
    asm volatile("cp.async.cg.shared.global [%0], [%1], 16;" :: "r"(dst_u32), "l"(src_ptr))
#define CP_COMMIT() asm volatile("cp.async.commit_group;" ::: "memory")
#define CP_WAIT1()  asm volatile("cp.async.wait_group 1;" ::: "memory")

__device__ __forceinline__ void mma16816(float* c, const uint32_t* a, const uint32_t* b) {
    asm volatile(
        "mma.sync.aligned.m16n8k16.row.col.f32.bf16.bf16.f32 "
        "{%0,%1,%2,%3}, {%4,%5,%6,%7}, {%8,%9}, {%0,%1,%2,%3};"
        : "+f"(c[0]), "+f"(c[1]), "+f"(c[2]), "+f"(c[3])
        : "r"(a[0]), "r"(a[1]), "r"(a[2]), "r"(a[3]), "r"(b[0]), "r"(b[1]));
}

// ---------------------------------------------------------------------------
// Hi/lo splitters.  in: [rows][512] f32  ->  out: [rows][1536] bf16
//   split3_a : [hi | lo | hi]  (activations, left operand)
//   split3_w : [hi | hi | lo]  (weights,     right operand)
// Product per row-pair: xhi*Whi + xlo*Whi + xhi*Wlo  (drops xlo*Wlo ~ 2^-18)
// ---------------------------------------------------------------------------
__device__ __forceinline__ void split_core(const float* __restrict__ in, int idx,
                                           int& r, int& c, uint2& H, uint2& L)
{
    r = idx >> 7;
    c = (idx & 127) << 2;
    float4 v = *reinterpret_cast<const float4*>(in + (size_t)r * CC + c);
    float f[4] = {v.x, v.y, v.z, v.w};
    uint32_t h[2], l[2];
    #pragma unroll
    for (int i = 0; i < 2; i++) {
        __nv_bfloat16 h0 = __float2bfloat16(f[2*i]);
        __nv_bfloat16 h1 = __float2bfloat16(f[2*i + 1]);
        __nv_bfloat16 l0 = __float2bfloat16(f[2*i]     - __bfloat162float(h0));
        __nv_bfloat16 l1 = __float2bfloat16(f[2*i + 1] - __bfloat162float(h1));
        h[i] = (uint32_t)__bfloat16_as_ushort(h0) | ((uint32_t)__bfloat16_as_ushort(h1) << 16);
        l[i] = (uint32_t)__bfloat16_as_ushort(l0) | ((uint32_t)__bfloat16_as_ushort(l1) << 16);
    }
    H = make_uint2(h[0], h[1]);
    L = make_uint2(l[0], l[1]);
}

__global__ void split3_a(const float* __restrict__ in, __nv_bfloat16* __restrict__ out, int rows)
{
    int idx = blockIdx.x * 256 + threadIdx.x;
    if (idx >= rows * 128) return;
    int r, c; uint2 H, L;
    split_core(in, idx, r, c, H, L);
    size_t base = (size_t)r * KK;
    *reinterpret_cast<uint2*>(out + base + c)        = H;   // hi
    *reinterpret_cast<uint2*>(out + base + 512 + c)  = L;   // lo
    *reinterpret_cast<uint2*>(out + base + 1024 + c) = H;   // hi
}

__global__ void split3_w(const float* __restrict__ in, __nv_bfloat16* __restrict__ out, int rows)
{
    int idx = blockIdx.x * 256 + threadIdx.x;
    if (idx >= rows * 128) return;
    int r, c; uint2 H, L;
    split_core(in, idx, r, c, H, L);
    size_t base = (size_t)r * KK;
    *reinterpret_cast<uint2*>(out + base + c)        = H;   // hi
    *reinterpret_cast<uint2*>(out + base + 512 + c)  = H;   // hi
    *reinterpret_cast<uint2*>(out + base + 1024 + c) = L;   // lo
}

// ---------------------------------------------------------------------------
// HMMA GEMM: C[M,N] = A[M,K] @ B[N,K]^T (+bias).  A,B bf16 K-contiguous, K=1536.
// CTA 128x128, BK=32, 3-stage cp.async pipeline.
// 8 warps (2 m x 4 n), warp tile 64x32, m16n8k16 fragments, fp32 accum.
// smem rows padded to 40 bf16 (80B) -> conflict-free 32-bit fragment loads.
// ---------------------------------------------------------------------------
#define BK      32
#define PAD     40
#define STAGES  3
#define TILEBF  (128 * PAD)            // bf16 per tile per stage
#define STAGEB  (2 * TILEBF * 2)       // bytes per stage (A + B)
#define NKCH    (KK / BK)              // 48

__global__ void __launch_bounds__(256, 2)
gemm_hmma(const __nv_bfloat16* __restrict__ Ag,
          const __nv_bfloat16* __restrict__ Bg,
          float* __restrict__ C, int ldc, const float* __restrict__ bias)
{
    extern __shared__ __align__(16) char smem[];
    __nv_bfloat16* As = reinterpret_cast<__nv_bfloat16*>(smem);              // [S][128][PAD]
    __nv_bfloat16* Bs = As + STAGES * TILEBF;                                // [S][128][PAD]
    const uint32_t sbase = smem_u32(smem);

    const int tid  = threadIdx.x;
    const int wid  = tid >> 5;
    const int lane = tid & 31;
    const int g    = lane >> 2;        // 0..7
    const int tig  = lane & 3;         // 0..3

    const int bm = blockIdx.y * 128;
    const int bn = blockIdx.x * 128;
    const int wm = (wid & 1) * 64;     // warp m offset
    const int wn = (wid >> 1) * 32;    // warp n offset

    const int r0 = tid >> 1;                 // 0..127
    const int c0 = (tid & 1) * 16;           // 0 or 16

    auto load_stage = [&](int kt, int s) {
        const uint32_t aoff = sbase + (uint32_t)(s * TILEBF + r0 * PAD + c0) * 2;
        const uint32_t boff = aoff + (uint32_t)(STAGES * TILEBF) * 2;
        const __nv_bfloat16* ap = Ag + (size_t)(bm + r0) * KK + kt * BK + c0;
        const __nv_bfloat16* bp = Bg + (size_t)(bn + r0) * KK + kt * BK + c0;
        CP16(aoff,      ap);
        CP16(aoff + 16, ap + 8);
        CP16(boff,      bp);
        CP16(boff + 16, bp + 8);
    };

    float acc[4][4][4] = {};

    load_stage(0, 0); CP_COMMIT();
    load_stage(1, 1); CP_COMMIT();

    for (int kt = 0; kt < NKCH; kt++) {
        CP_WAIT1();
        __syncthreads();

        const int nk = kt + STAGES - 1;
        if (nk < NKCH) load_stage(nk, nk % STAGES);
        CP_COMMIT();

        const __nv_bfloat16* at = As + (kt % STAGES) * TILEBF;
        const __nv_bfloat16* bt = Bs + (kt % STAGES) * TILEBF;

        #pragma unroll
        for (int kk = 0; kk < BK; kk += 16) {
            uint32_t af[4][4], bf[4][2];
            #pragma unroll
            for (int mi = 0; mi < 4; mi++) {
                const int ar = wm + mi * 16 + g;
                const __nv_bfloat16* p = at + ar * PAD + kk + tig * 2;
                af[mi][0] = *reinterpret_cast<const uint32_t*>(p);
                af[mi][1] = *reinterpret_cast<const uint32_t*>(p + 8 * PAD);
                af[mi][2] = *reinterpret_cast<const uint32_t*>(p + 8);
                af[mi][3] = *reinterpret_cast<const uint32_t*>(p + 8 * PAD + 8);
            }
            #pragma unroll
            for (int ni = 0; ni < 4; ni++) {
                const int br = wn + ni * 8 + g;
                const __nv_bfloat16* p = bt + br * PAD + kk + tig * 2;
                bf[ni][0] = *reinterpret_cast<const uint32_t*>(p);
                bf[ni][1] = *reinterpret_cast<const uint32_t*>(p + 8);
            }
            #pragma unroll
            for (int mi = 0; mi < 4; mi++)
                #pragma unroll
                for (int ni = 0; ni < 4; ni++)
                    mma16816(acc[mi][ni], af[mi], bf[ni]);
        }
        __syncthreads();
    }

    // ---- epilogue ----
    #pragma unroll
    for (int mi = 0; mi < 4; mi++) {
        const int row0 = bm + wm + mi * 16 + g;
        #pragma unroll
        for (int ni = 0; ni < 4; ni++) {
            const int col = bn + wn + ni * 8 + tig * 2;
            float b0 = 0.f, b1 = 0.f;
            if (bias) { b0 = bias[col]; b1 = bias[col + 1]; }
            float2 lo = make_float2(acc[mi][ni][0] + b0, acc[mi][ni][1] + b1);
            float2 hi = make_float2(acc[mi][ni][2] + b0, acc[mi][ni][3] + b1);
            *reinterpret_cast<float2*>(C + (size_t)row0 * ldc + col)       = lo;
            *reinterpret_cast<float2*>(C + (size_t)(row0 + 8) * ldc + col) = hi;
        }
    }
}

// ---------------------------------------------------------------------------
// Sparse triplane attention (64 keys/query, closed-form indices).
// q/k/v interleaved per row in g_qkv: [row][ q(512) | k(512) | v(512) ].
// ---------------------------------------------------------------------------
__global__ void attn_kernel(const float* __restrict__ qkv, float* __restrict__ o)
{
    __shared__ float sc[HH][64];

    const int bn   = blockIdx.x;
    const int b    = bn / NN;
    const int n    = bn % NN;
    const int h    = threadIdx.x >> 5;
    const int lane = threadIdx.x & 31;

    const int p   = n >> 10;
    const int rem = n & 1023;
    const int i   = rem >> 5;
    const int j   = rem & 31;

    int base0, st0, base1, st1;
    if (p == 0)      { base0 = 1024 + i * 32; st0 = 1;  base1 = 2048 + j * 32; st1 = 1;  }
    else if (p == 1) { base0 = i * 32;        st0 = 1;  base1 = 2048 + j;      st1 = 32; }
    else             { base0 = i;             st0 = 32; base1 = 1024 + j;      st1 = 32; }

    const size_t rowbase = (size_t)b * NN * NQKV;
    const float* qrow = qkv + rowbase + (size_t)n * NQKV + h * DD;
    const float q0 = qrow[lane];
    const float q1 = qrow[lane + 32];

    for (int t = 0; t < 64; t++) {
        const int key = (t < 32) ? (base0 + t * st0) : (base1 + (t - 32) * st1);
        const float* krow = qkv + rowbase + (size_t)key * NQKV + 512 + h * DD;
        float pa = q0 * krow[lane] + q1 * krow[lane + 32];
        #pragma unroll
        for (int off = 16; off; off >>= 1)
            pa += __shfl_xor_sync(0xffffffffu, pa, off);
        if (lane == 0) sc[h][t] = pa * 0.125f;
    }
    __syncwarp();

    float s0 = sc[h][lane], s1 = sc[h][lane + 32];
    float m = fmaxf(s0, s1);
    #pragma unroll
    for (int off = 16; off; off >>= 1)
        m = fmaxf(m, __shfl_xor_sync(0xffffffffu, m, off));
    float e0 = __expf(s0 - m), e1 = __expf(s1 - m);
    float sum = e0 + e1;
    #pragma unroll
    for (int off = 16; off; off >>= 1)
        sum += __shfl_xor_sync(0xffffffffu, sum, off);
    const float inv = 1.0f / sum;
    sc[h][lane]      = e0 * inv;
    sc[h][lane + 32] = e1 * inv;
    __syncwarp();

    float a0 = 0.f, a1 = 0.f;
    for (int t = 0; t < 64; t++) {
        const int key = (t < 32) ? (base0 + t * st0) : (base1 + (t - 32) * st1);
        const float* vrow = qkv + rowbase + (size_t)key * NQKV + 1024 + h * DD;
        const float pt = sc[h][t];
        a0 += pt * vrow[lane];
        a1 += pt * vrow[lane + 32];
    }

    float* orow = o + (size_t)(b * NN + n) * CC + h * DD;
    orow[lane]      = a0;
    orow[lane + 32] = a1;
}

// ---------------------------------------------------------------------------
// Host side
// ---------------------------------------------------------------------------
extern "C" void kernel_launch(void* const* d_in, const int* in_sizes, int n_in,
                              void* d_out, int out_size)
{
    const float* x  = (const float*)d_in[0];
    const float* Wq = (const float*)d_in[1];
    const float* Wk = (const float*)d_in[2];
    const float* Wv = (const float*)d_in[3];
    const float* Wp = (const float*)d_in[4];
    const float* bp = (const float*)d_in[5];
    float* out = (float*)d_out;

    __nv_bfloat16 *A, *Bq, *Bo;
    float *qkv, *att;
    cudaGetSymbolAddress((void**)&A,   g_A);
    cudaGetSymbolAddress((void**)&Bq,  g_Bqkv);
    cudaGetSymbolAddress((void**)&Bo,  g_Bout);
    cudaGetSymbolAddress((void**)&qkv, g_qkv);
    cudaGetSymbolAddress((void**)&att, g_att);

    constexpr int SMEM = STAGES * STAGEB;   // 61440
    static bool s_attr = false;
    if (!s_attr) {
        cudaFuncSetAttribute(gemm_hmma, cudaFuncAttributeMaxDynamicSharedMemorySize, SMEM);
        s_attr = true;
    }

    // 1) hi/lo splits: activations [hi|lo|hi], weights [hi|hi|lo]
    split3_a<<<(MM * 128 + 255) / 256, 256>>>(x, A, MM);
    split3_w<<<(CC * 128 + 255) / 256, 256>>>(Wq, Bq,                     CC);
    split3_w<<<(CC * 128 + 255) / 256, 256>>>(Wk, Bq + (size_t)512 * KK,  CC);
    split3_w<<<(CC * 128 + 255) / 256, 256>>>(Wv, Bq + (size_t)1024 * KK, CC);
    split3_w<<<(CC * 128 + 255) / 256, 256>>>(Wp, Bo,                     CC);

    // 2) fused QKV projection: [6144,1536] = A @ Bqkv^T
    gemm_hmma<<<dim3(NQKV / 128, MM / 128), 256, SMEM>>>(A, Bq, qkv, NQKV, nullptr);

    // 3) sparse triplane attention
    attn_kernel<<<MM, HH * 32>>>(qkv, att);

    // 4) split attention output, output projection with bias
    split3_a<<<(MM * 128 + 255) / 256, 256>>>(att, A, MM);
    gemm_hmma<<<dim3(CC / 128, MM / 128), 256, SMEM>>>(A, Bo, out, CC, bp);
}

// round 6
// speedup vs baseline: 1.9321x; 1.0796x over previous
#include <cuda_runtime.h>
#include <cuda_bf16.h>
#include <cstdint>
#include <cstddef>

#define NB   2
#define NN   3072
#define CC   512
#define MM   (NB * NN)      // 6144
#define HH   8
#define DD   64
#define KK   1536           // split-K: A=[hi|lo|hi], B=[hi|hi|lo]
#define NQKV 1536

// ---------------------------------------------------------------------------
// Device scratch
// ---------------------------------------------------------------------------
__device__ __align__(1024) __nv_bfloat16 g_A[(size_t)MM * KK];      // split activations
__device__ __align__(1024) __nv_bfloat16 g_Bqkv[(size_t)NQKV * KK]; // [Wq;Wk;Wv] split
__device__ __align__(1024) __nv_bfloat16 g_Bout[(size_t)CC * KK];   // Wp split
__device__ __align__(16)   float g_qkv[(size_t)MM * NQKV];          // q|k|v fp32

// ---------------------------------------------------------------------------
// helpers
// ---------------------------------------------------------------------------
__device__ __forceinline__ uint32_t smem_u32(const void* p) {
    uint32_t a;
    asm("{ .reg .u64 t; cvta.to.shared.u64 t, %1; cvt.u32.u64 %0, t; }" : "=r"(a) : "l"(p));
    return a;
}

#define CP16(dst_u32, src_ptr) \
    asm volatile("cp.async.cg.shared.global [%0], [%1], 16;" :: "r"(dst_u32), "l"(src_ptr))
#define CP_COMMIT()  asm volatile("cp.async.commit_group;" ::: "memory")
#define CP_WAITG(n)  asm volatile("cp.async.wait_group %0;" :: "n"(n) : "memory")

#define LDSM_X4(r0, r1, r2, r3, addr) \
    asm volatile("ldmatrix.sync.aligned.m8n8.x4.shared.b16 {%0,%1,%2,%3}, [%4];" \
                 : "=r"(r0), "=r"(r1), "=r"(r2), "=r"(r3) : "r"(addr))

__device__ __forceinline__ void mma16816(float* c, const uint32_t* a, const uint32_t* b) {
    asm volatile(
        "mma.sync.aligned.m16n8k16.row.col.f32.bf16.bf16.f32 "
        "{%0,%1,%2,%3}, {%4,%5,%6,%7}, {%8,%9}, {%0,%1,%2,%3};"
        : "+f"(c[0]), "+f"(c[1]), "+f"(c[2]), "+f"(c[3])
        : "r"(a[0]), "r"(a[1]), "r"(a[2]), "r"(a[3]), "r"(b[0]), "r"(b[1]));
}

// ---------------------------------------------------------------------------
// Hi/lo splitters:  split3_a -> [hi|lo|hi] (activations), split3_w -> [hi|hi|lo]
// Product: xhi*Whi + xlo*Whi + xhi*Wlo   (drops xlo*Wlo ~2^-18)
// ---------------------------------------------------------------------------
__device__ __forceinline__ void split_core(const float* __restrict__ in, int idx,
                                           int& r, int& c, uint2& H, uint2& L)
{
    r = idx >> 7;
    c = (idx & 127) << 2;
    float4 v = *reinterpret_cast<const float4*>(in + (size_t)r * CC + c);
    float f[4] = {v.x, v.y, v.z, v.w};
    uint32_t h[2], l[2];
    #pragma unroll
    for (int i = 0; i < 2; i++) {
        __nv_bfloat16 h0 = __float2bfloat16(f[2*i]);
        __nv_bfloat16 h1 = __float2bfloat16(f[2*i + 1]);
        __nv_bfloat16 l0 = __float2bfloat16(f[2*i]     - __bfloat162float(h0));
        __nv_bfloat16 l1 = __float2bfloat16(f[2*i + 1] - __bfloat162float(h1));
        h[i] = (uint32_t)__bfloat16_as_ushort(h0) | ((uint32_t)__bfloat16_as_ushort(h1) << 16);
        l[i] = (uint32_t)__bfloat16_as_ushort(l0) | ((uint32_t)__bfloat16_as_ushort(l1) << 16);
    }
    H = make_uint2(h[0], h[1]);
    L = make_uint2(l[0], l[1]);
}

__global__ void split3_a(const float* __restrict__ in, __nv_bfloat16* __restrict__ out, int rows)
{
    int idx = blockIdx.x * 256 + threadIdx.x;
    if (idx >= rows * 128) return;
    int r, c; uint2 H, L;
    split_core(in, idx, r, c, H, L);
    size_t base = (size_t)r * KK;
    *reinterpret_cast<uint2*>(out + base + c)        = H;
    *reinterpret_cast<uint2*>(out + base + 512 + c)  = L;
    *reinterpret_cast<uint2*>(out + base + 1024 + c) = H;
}

__global__ void split3_w(const float* __restrict__ in, __nv_bfloat16* __restrict__ out, int rows)
{
    int idx = blockIdx.x * 256 + threadIdx.x;
    if (idx >= rows * 128) return;
    int r, c; uint2 H, L;
    split_core(in, idx, r, c, H, L);
    size_t base = (size_t)r * KK;
    *reinterpret_cast<uint2*>(out + base + c)        = H;
    *reinterpret_cast<uint2*>(out + base + 512 + c)  = H;
    *reinterpret_cast<uint2*>(out + base + 1024 + c) = L;
}

// ---------------------------------------------------------------------------
// HMMA GEMM: C[M,N] = A[M,K] @ B[N,K]^T (+bias).  bf16 K-contiguous, K=1536.
// CTA 128x128, BK=32, 4-stage cp.async pipeline, ldmatrix fragment loads.
// 8 warps (2m x 4n), warp tile 64x32, m16n8k16, fp32 accum.
// PAD=40 (80B rows): ldmatrix 8-row groups hit distinct 16B banks (stride 5 mod 8).
// ---------------------------------------------------------------------------
#define BK      32
#define PAD     40
#define STAGES  4
#define TILEBF  (128 * PAD)
#define STAGEB  (2 * TILEBF * 2)
#define NKCH    (KK / BK)              // 48

__global__ void __launch_bounds__(256, 2)
gemm_hmma(const __nv_bfloat16* __restrict__ Ag,
          const __nv_bfloat16* __restrict__ Bg,
          float* __restrict__ C, int ldc, const float* __restrict__ bias)
{
    extern __shared__ __align__(16) char smem[];
    const uint32_t sbase = smem_u32(smem);

    const int tid  = threadIdx.x;
    const int wid  = tid >> 5;
    const int lane = tid & 31;
    const int g    = lane >> 2;
    const int tig  = lane & 3;

    const int bm = blockIdx.y * 128;
    const int bn = blockIdx.x * 128;
    const int wm = (wid & 1) * 64;
    const int wn = (wid >> 1) * 32;

    const int r0 = tid >> 1;
    const int c0 = (tid & 1) * 16;

    auto load_stage = [&](int kt, int s) {
        const uint32_t aoff = sbase + (uint32_t)(s * TILEBF + r0 * PAD + c0) * 2;
        const uint32_t boff = aoff + (uint32_t)(STAGES * TILEBF) * 2;
        const __nv_bfloat16* ap = Ag + (size_t)(bm + r0) * KK + kt * BK + c0;
        const __nv_bfloat16* bp = Bg + (size_t)(bn + r0) * KK + kt * BK + c0;
        CP16(aoff,      ap);
        CP16(aoff + 16, ap + 8);
        CP16(boff,      bp);
        CP16(boff + 16, bp + 8);
    };

    // per-lane ldmatrix base offsets (bytes)
    const uint32_t a_off = (uint32_t)((wm + (lane & 15)) * PAD + (lane >> 4) * 8) * 2;
    const uint32_t b_off = (uint32_t)((wn + (lane >> 4) * 8 + (lane & 7)) * PAD
                                      + ((lane >> 3) & 1) * 8) * 2;

    float acc[4][4][4] = {};

    load_stage(0, 0); CP_COMMIT();
    load_stage(1, 1); CP_COMMIT();
    load_stage(2, 2); CP_COMMIT();

    for (int kt = 0; kt < NKCH; kt++) {
        CP_WAITG(2);
        __syncthreads();

        const int nk = kt + STAGES - 1;
        if (nk < NKCH) load_stage(nk, nk & 3);
        CP_COMMIT();

        const uint32_t at = sbase + (uint32_t)((kt & 3) * TILEBF) * 2 + a_off;
        const uint32_t bt = sbase + (uint32_t)((STAGES + (kt & 3)) * TILEBF) * 2 + b_off;

        #pragma unroll
        for (int kk = 0; kk < BK; kk += 16) {
            uint32_t af[4][4], bf[4][2];
            #pragma unroll
            for (int mi = 0; mi < 4; mi++)
                LDSM_X4(af[mi][0], af[mi][1], af[mi][2], af[mi][3],
                        at + (uint32_t)(mi * 16 * PAD + kk) * 2);
            #pragma unroll
            for (int np = 0; np < 2; np++)
                LDSM_X4(bf[2*np][0], bf[2*np][1], bf[2*np+1][0], bf[2*np+1][1],
                        bt + (uint32_t)(np * 16 * PAD + kk) * 2);
            #pragma unroll
            for (int mi = 0; mi < 4; mi++)
                #pragma unroll
                for (int ni = 0; ni < 4; ni++)
                    mma16816(acc[mi][ni], af[mi], bf[ni]);
        }
        __syncthreads();
    }

    // ---- epilogue ----
    #pragma unroll
    for (int mi = 0; mi < 4; mi++) {
        const int row0 = bm + wm + mi * 16 + g;
        #pragma unroll
        for (int ni = 0; ni < 4; ni++) {
            const int col = bn + wn + ni * 8 + tig * 2;
            float b0 = 0.f, b1 = 0.f;
            if (bias) { b0 = bias[col]; b1 = bias[col + 1]; }
            float2 lo = make_float2(acc[mi][ni][0] + b0, acc[mi][ni][1] + b1);
            float2 hi = make_float2(acc[mi][ni][2] + b0, acc[mi][ni][3] + b1);
            *reinterpret_cast<float2*>(C + (size_t)row0 * ldc + col)       = lo;
            *reinterpret_cast<float2*>(C + (size_t)(row0 + 8) * ldc + col) = hi;
        }
    }
}

// ---------------------------------------------------------------------------
// Sparse triplane attention (64 keys/query).  Reads fp32 qkv rows
// [q|k|v] of 1536; writes the output DIRECTLY as [hi|lo|hi] bf16 rows of
// g_A (fusing the split for the output projection).
// ---------------------------------------------------------------------------
__global__ void attn_kernel(const float* __restrict__ qkv, __nv_bfloat16* __restrict__ Aout)
{
    __shared__ float sc[HH][64];

    const int bn   = blockIdx.x;
    const int b    = bn / NN;
    const int n    = bn % NN;
    const int h    = threadIdx.x >> 5;
    const int lane = threadIdx.x & 31;

    const int p   = n >> 10;
    const int rem = n & 1023;
    const int i   = rem >> 5;
    const int j   = rem & 31;

    int base0, st0, base1, st1;
    if (p == 0)      { base0 = 1024 + i * 32; st0 = 1;  base1 = 2048 + j * 32; st1 = 1;  }
    else if (p == 1) { base0 = i * 32;        st0 = 1;  base1 = 2048 + j;      st1 = 32; }
    else             { base0 = i;             st0 = 32; base1 = 1024 + j;      st1 = 32; }

    const size_t rowbase = (size_t)b * NN * NQKV;
    const float* qrow = qkv + rowbase + (size_t)n * NQKV + h * DD;
    const float q0 = qrow[lane];
    const float q1 = qrow[lane + 32];

    for (int t = 0; t < 64; t++) {
        const int key = (t < 32) ? (base0 + t * st0) : (base1 + (t - 32) * st1);
        const float* krow = qkv + rowbase + (size_t)key * NQKV + 512 + h * DD;
        float pa = q0 * krow[lane] + q1 * krow[lane + 32];
        #pragma unroll
        for (int off = 16; off; off >>= 1)
            pa += __shfl_xor_sync(0xffffffffu, pa, off);
        if (lane == 0) sc[h][t] = pa * 0.125f;
    }
    __syncwarp();

    float s0 = sc[h][lane], s1 = sc[h][lane + 32];
    float m = fmaxf(s0, s1);
    #pragma unroll
    for (int off = 16; off; off >>= 1)
        m = fmaxf(m, __shfl_xor_sync(0xffffffffu, m, off));
    float e0 = __expf(s0 - m), e1 = __expf(s1 - m);
    float sum = e0 + e1;
    #pragma unroll
    for (int off = 16; off; off >>= 1)
        sum += __shfl_xor_sync(0xffffffffu, sum, off);
    const float inv = 1.0f / sum;
    sc[h][lane]      = e0 * inv;
    sc[h][lane + 32] = e1 * inv;
    __syncwarp();

    float a0 = 0.f, a1 = 0.f;
    for (int t = 0; t < 64; t++) {
        const int key = (t < 32) ? (base0 + t * st0) : (base1 + (t - 32) * st1);
        const float* vrow = qkv + rowbase + (size_t)key * NQKV + 1024 + h * DD;
        const float pt = sc[h][t];
        a0 += pt * vrow[lane];
        a1 += pt * vrow[lane + 32];
    }

    // fused [hi|lo|hi] split write
    const size_t ab = (size_t)(b * NN + n) * KK + h * DD;
    __nv_bfloat16 h0 = __float2bfloat16(a0);
    __nv_bfloat16 l0 = __float2bfloat16(a0 - __bfloat162float(h0));
    __nv_bfloat16 h1 = __float2bfloat16(a1);
    __nv_bfloat16 l1 = __float2bfloat16(a1 - __bfloat162float(h1));
    Aout[ab + lane]             = h0;
    Aout[ab + 512 + lane]       = l0;
    Aout[ab + 1024 + lane]      = h0;
    Aout[ab + lane + 32]        = h1;
    Aout[ab + 512 + lane + 32]  = l1;
    Aout[ab + 1024 + lane + 32] = h1;
}

// ---------------------------------------------------------------------------
// Host side
// ---------------------------------------------------------------------------
extern "C" void kernel_launch(void* const* d_in, const int* in_sizes, int n_in,
                              void* d_out, int out_size)
{
    const float* x  = (const float*)d_in[0];
    const float* Wq = (const float*)d_in[1];
    const float* Wk = (const float*)d_in[2];
    const float* Wv = (const float*)d_in[3];
    const float* Wp = (const float*)d_in[4];
    const float* bp = (const float*)d_in[5];
    float* out = (float*)d_out;

    __nv_bfloat16 *A, *Bq, *Bo;
    float *qkv;
    cudaGetSymbolAddress((void**)&A,   g_A);
    cudaGetSymbolAddress((void**)&Bq,  g_Bqkv);
    cudaGetSymbolAddress((void**)&Bo,  g_Bout);
    cudaGetSymbolAddress((void**)&qkv, g_qkv);

    constexpr int SMEM = STAGES * STAGEB;   // 4 * 20480 = 81920
    static bool s_attr = false;
    if (!s_attr) {
        cudaFuncSetAttribute(gemm_hmma, cudaFuncAttributeMaxDynamicSharedMemorySize, SMEM);
        s_attr = true;
    }

    // 1) hi/lo splits
    split3_a<<<(MM * 128 + 255) / 256, 256>>>(x, A, MM);
    split3_w<<<(CC * 128 + 255) / 256, 256>>>(Wq, Bq,                     CC);
    split3_w<<<(CC * 128 + 255) / 256, 256>>>(Wk, Bq + (size_t)512 * KK,  CC);
    split3_w<<<(CC * 128 + 255) / 256, 256>>>(Wv, Bq + (size_t)1024 * KK, CC);
    split3_w<<<(CC * 128 + 255) / 256, 256>>>(Wp, Bo,                     CC);

    // 2) fused QKV projection
    gemm_hmma<<<dim3(NQKV / 128, MM / 128), 256, SMEM>>>(A, Bq, qkv, NQKV, nullptr);

    // 3) sparse triplane attention (writes split A directly)
    attn_kernel<<<MM, HH * 32>>>(qkv, A);

    // 4) output projection with bias
    gemm_hmma<<<dim3(CC / 128, MM / 128), 256, SMEM>>>(A, Bo, out, CC, bp);
}

// round 7
// speedup vs baseline: 2.0850x; 1.0791x over previous
#include <cuda_runtime.h>
#include <cuda_bf16.h>
#include <cstdint>
#include <cstddef>

#define NB   2
#define NN   3072
#define CC   512
#define MM   (NB * NN)      // 6144
#define HH   8
#define DD   64
#define KK   1536           // split-K: A=[hi|lo|hi], B=[hi|hi|lo]
#define NQKV 1536

// ---------------------------------------------------------------------------
// Device scratch
// ---------------------------------------------------------------------------
__device__ __align__(1024) __nv_bfloat16 g_A[(size_t)MM * KK];      // split activations
__device__ __align__(1024) __nv_bfloat16 g_Bqkv[(size_t)NQKV * KK]; // [Wq;Wk;Wv] split
__device__ __align__(1024) __nv_bfloat16 g_Bout[(size_t)CC * KK];   // Wp split
__device__ __align__(16)   float g_qkv[(size_t)MM * NQKV];          // q|k|v fp32

// ---------------------------------------------------------------------------
// helpers
// ---------------------------------------------------------------------------
__device__ __forceinline__ uint32_t smem_u32(const void* p) {
    uint32_t a;
    asm("{ .reg .u64 t; cvta.to.shared.u64 t, %1; cvt.u32.u64 %0, t; }" : "=r"(a) : "l"(p));
    return a;
}

#define CP16(dst_u32, src_ptr) \
    asm volatile("cp.async.cg.shared.global [%0], [%1], 16;" :: "r"(dst_u32), "l"(src_ptr))
#define CP_COMMIT()  asm volatile("cp.async.commit_group;" ::: "memory")
#define CP_WAITG(n)  asm volatile("cp.async.wait_group %0;" :: "n"(n) : "memory")

#define LDSM_X4(r0, r1, r2, r3, addr) \
    asm volatile("ldmatrix.sync.aligned.m8n8.x4.shared.b16 {%0,%1,%2,%3}, [%4];" \
                 : "=r"(r0), "=r"(r1), "=r"(r2), "=r"(r3) : "r"(addr))

__device__ __forceinline__ void mma16816(float* c, const uint32_t* a, const uint32_t* b) {
    asm volatile(
        "mma.sync.aligned.m16n8k16.row.col.f32.bf16.bf16.f32 "
        "{%0,%1,%2,%3}, {%4,%5,%6,%7}, {%8,%9}, {%0,%1,%2,%3};"
        : "+f"(c[0]), "+f"(c[1]), "+f"(c[2]), "+f"(c[3])
        : "r"(a[0]), "r"(a[1]), "r"(a[2]), "r"(a[3]), "r"(b[0]), "r"(b[1]));
}

// ---------------------------------------------------------------------------
// Hi/lo splitters:  split3_a -> [hi|lo|hi], split3_w -> [hi|hi|lo]
// ---------------------------------------------------------------------------
__device__ __forceinline__ void split_core(const float* __restrict__ in, int idx,
                                           int& r, int& c, uint2& H, uint2& L)
{
    r = idx >> 7;
    c = (idx & 127) << 2;
    float4 v = *reinterpret_cast<const float4*>(in + (size_t)r * CC + c);
    float f[4] = {v.x, v.y, v.z, v.w};
    uint32_t h[2], l[2];
    #pragma unroll
    for (int i = 0; i < 2; i++) {
        __nv_bfloat16 h0 = __float2bfloat16(f[2*i]);
        __nv_bfloat16 h1 = __float2bfloat16(f[2*i + 1]);
        __nv_bfloat16 l0 = __float2bfloat16(f[2*i]     - __bfloat162float(h0));
        __nv_bfloat16 l1 = __float2bfloat16(f[2*i + 1] - __bfloat162float(h1));
        h[i] = (uint32_t)__bfloat16_as_ushort(h0) | ((uint32_t)__bfloat16_as_ushort(h1) << 16);
        l[i] = (uint32_t)__bfloat16_as_ushort(l0) | ((uint32_t)__bfloat16_as_ushort(l1) << 16);
    }
    H = make_uint2(h[0], h[1]);
    L = make_uint2(l[0], l[1]);
}

__global__ void split3_a(const float* __restrict__ in, __nv_bfloat16* __restrict__ out, int rows)
{
    int idx = blockIdx.x * 256 + threadIdx.x;
    if (idx >= rows * 128) return;
    int r, c; uint2 H, L;
    split_core(in, idx, r, c, H, L);
    size_t base = (size_t)r * KK;
    *reinterpret_cast<uint2*>(out + base + c)        = H;
    *reinterpret_cast<uint2*>(out + base + 512 + c)  = L;
    *reinterpret_cast<uint2*>(out + base + 1024 + c) = H;
}

__global__ void split3_w(const float* __restrict__ in, __nv_bfloat16* __restrict__ out, int rows)
{
    int idx = blockIdx.x * 256 + threadIdx.x;
    if (idx >= rows * 128) return;
    int r, c; uint2 H, L;
    split_core(in, idx, r, c, H, L);
    size_t base = (size_t)r * KK;
    *reinterpret_cast<uint2*>(out + base + c)        = H;
    *reinterpret_cast<uint2*>(out + base + 512 + c)  = H;
    *reinterpret_cast<uint2*>(out + base + 1024 + c) = L;
}

// ---------------------------------------------------------------------------
// HMMA GEMM (unchanged from R6): CTA 128x128, BK=32, 4-stage cp.async,
// ldmatrix fragment loads, 8 warps, warp tile 64x32, fp32 accum.
// ---------------------------------------------------------------------------
#define BK      32
#define PAD     40
#define STAGES  4
#define TILEBF  (128 * PAD)
#define STAGEB  (2 * TILEBF * 2)
#define NKCH    (KK / BK)              // 48

__global__ void __launch_bounds__(256, 2)
gemm_hmma(const __nv_bfloat16* __restrict__ Ag,
          const __nv_bfloat16* __restrict__ Bg,
          float* __restrict__ C, int ldc, const float* __restrict__ bias)
{
    extern __shared__ __align__(16) char smem[];
    const uint32_t sbase = smem_u32(smem);

    const int tid  = threadIdx.x;
    const int wid  = tid >> 5;
    const int lane = tid & 31;
    const int g    = lane >> 2;
    const int tig  = lane & 3;

    const int bm = blockIdx.y * 128;
    const int bn = blockIdx.x * 128;
    const int wm = (wid & 1) * 64;
    const int wn = (wid >> 1) * 32;

    const int r0 = tid >> 1;
    const int c0 = (tid & 1) * 16;

    auto load_stage = [&](int kt, int s) {
        const uint32_t aoff = sbase + (uint32_t)(s * TILEBF + r0 * PAD + c0) * 2;
        const uint32_t boff = aoff + (uint32_t)(STAGES * TILEBF) * 2;
        const __nv_bfloat16* ap = Ag + (size_t)(bm + r0) * KK + kt * BK + c0;
        const __nv_bfloat16* bp = Bg + (size_t)(bn + r0) * KK + kt * BK + c0;
        CP16(aoff,      ap);
        CP16(aoff + 16, ap + 8);
        CP16(boff,      bp);
        CP16(boff + 16, bp + 8);
    };

    const uint32_t a_off = (uint32_t)((wm + (lane & 15)) * PAD + (lane >> 4) * 8) * 2;
    const uint32_t b_off = (uint32_t)((wn + (lane >> 4) * 8 + (lane & 7)) * PAD
                                      + ((lane >> 3) & 1) * 8) * 2;

    float acc[4][4][4] = {};

    load_stage(0, 0); CP_COMMIT();
    load_stage(1, 1); CP_COMMIT();
    load_stage(2, 2); CP_COMMIT();

    for (int kt = 0; kt < NKCH; kt++) {
        CP_WAITG(2);
        __syncthreads();

        const int nk = kt + STAGES - 1;
        if (nk < NKCH) load_stage(nk, nk & 3);
        CP_COMMIT();

        const uint32_t at = sbase + (uint32_t)((kt & 3) * TILEBF) * 2 + a_off;
        const uint32_t bt = sbase + (uint32_t)((STAGES + (kt & 3)) * TILEBF) * 2 + b_off;

        #pragma unroll
        for (int kk = 0; kk < BK; kk += 16) {
            uint32_t af[4][4], bf[4][2];
            #pragma unroll
            for (int mi = 0; mi < 4; mi++)
                LDSM_X4(af[mi][0], af[mi][1], af[mi][2], af[mi][3],
                        at + (uint32_t)(mi * 16 * PAD + kk) * 2);
            #pragma unroll
            for (int np = 0; np < 2; np++)
                LDSM_X4(bf[2*np][0], bf[2*np][1], bf[2*np+1][0], bf[2*np+1][1],
                        bt + (uint32_t)(np * 16 * PAD + kk) * 2);
            #pragma unroll
            for (int mi = 0; mi < 4; mi++)
                #pragma unroll
                for (int ni = 0; ni < 4; ni++)
                    mma16816(acc[mi][ni], af[mi], bf[ni]);
        }
        __syncthreads();
    }

    #pragma unroll
    for (int mi = 0; mi < 4; mi++) {
        const int row0 = bm + wm + mi * 16 + g;
        #pragma unroll
        for (int ni = 0; ni < 4; ni++) {
            const int col = bn + wn + ni * 8 + tig * 2;
            float b0 = 0.f, b1 = 0.f;
            if (bias) { b0 = bias[col]; b1 = bias[col + 1]; }
            float2 lo = make_float2(acc[mi][ni][0] + b0, acc[mi][ni][1] + b1);
            float2 hi = make_float2(acc[mi][ni][2] + b0, acc[mi][ni][3] + b1);
            *reinterpret_cast<float2*>(C + (size_t)row0 * ldc + col)       = lo;
            *reinterpret_cast<float2*>(C + (size_t)(row0 + 8) * ldc + col) = hi;
        }
    }
}

// ---------------------------------------------------------------------------
// Tiled sparse triplane attention.
// Block = (b, p, 4x4 query tile) -> 16 queries share a 256-key union
// (128 group0 rows + 128 group1 rows).  Heads processed sequentially;
// per head K and V slices staged in smem (pad 68: conflict-free + 16B align).
// Warp w handles queries 2w, 2w+1.  Probs stay in registers (shfl broadcast).
// Output written directly as [hi|lo|hi] bf16 rows of g_A.
// ---------------------------------------------------------------------------
#define QROW 520        // Qs row stride (floats)
#define KROW 68         // Ks/Vs row stride (floats)

__global__ void __launch_bounds__(256, 1)
attn_tile(const float* __restrict__ qkv, __nv_bfloat16* __restrict__ Aout)
{
    extern __shared__ __align__(16) float sm[];
    float* Qs = sm;                         // [16][QROW]
    float* Ks = sm + 16 * QROW;             // [256][KROW]
    float* Vs = Ks + 256 * KROW;            // [256][KROW]
    const uint32_t ks_base = smem_u32(Ks);
    const uint32_t vs_base = smem_u32(Vs);

    const int x  = blockIdx.x;              // 0..383
    const int b  = x / 192;
    const int r0 = x % 192;
    const int p  = r0 >> 6;
    const int t0 = r0 & 63;
    const int i0 = (t0 >> 3) << 2;
    const int j0 = (t0 & 7) << 2;

    const int tid  = threadIdx.x;
    const int wid  = tid >> 5;
    const int lane = tid & 31;

    const float* Bq = qkv + (size_t)b * NN * NQKV;

    // ---- load Q tile (all heads): 16 rows x 512 floats ----
    for (int idx = tid; idx < 16 * 128; idx += 256) {
        const int q  = idx >> 7;
        const int f4 = idx & 127;
        const int di = q >> 2, dj = q & 3;
        const int n  = (p << 10) + (i0 + di) * 32 + (j0 + dj);
        float4 v = *reinterpret_cast<const float4*>(Bq + (size_t)n * NQKV + f4 * 4);
        *reinterpret_cast<float4*>(Qs + q * QROW + f4 * 4) = v;
    }

    for (int h = 0; h < HH; h++) {
        __syncthreads();   // previous head's compute done before overwriting K/V

        // ---- stage K,V head slices: 2 x 256 rows x 64 floats via cp.async ----
        for (int idx = tid; idx < 2 * 256 * 16; idx += 256) {
            const int which = idx >> 12;         // 0 = K, 1 = V
            const int rr    = (idx >> 4) & 255;  // smem row
            const int c4    = idx & 15;
            const int rl    = rr & 127;
            int gr;
            if (p == 0)
                gr = (rr < 128) ? (1024 + 32 * i0 + rl) : (2048 + 32 * j0 + rl);
            else if (p == 1)
                gr = (rr < 128) ? (32 * i0 + rl)
                                : (2048 + 32 * (rl & 31) + j0 + (rl >> 5));
            else
                gr = (rr < 128) ? (32 * (rl & 31) + i0 + (rl >> 5))
                                : (1024 + 32 * (rl & 31) + j0 + (rl >> 5));
            const float* src = Bq + (size_t)gr * NQKV + 512 + which * 512 + h * DD + c4 * 4;
            const uint32_t dst = (which ? vs_base : ks_base) + (uint32_t)(rr * KROW + c4 * 4) * 4;
            CP16(dst, src);
        }
        CP_COMMIT();
        CP_WAITG(0);
        __syncthreads();

        // ---- compute: warp wid -> queries 2*wid, 2*wid+1 ----
        #pragma unroll
        for (int qq = 0; qq < 2; qq++) {
            const int q  = wid * 2 + qq;
            const int di = q >> 2, dj = q & 3;

            const float4* qv4 = reinterpret_cast<const float4*>(Qs + q * QROW + h * DD);
            const float4* k0  = reinterpret_cast<const float4*>(Ks + (di * 32 + lane) * KROW);
            const float4* k1  = reinterpret_cast<const float4*>(Ks + (128 + dj * 32 + lane) * KROW);

            float a0 = 0.f, a1 = 0.f;
            #pragma unroll
            for (int d4 = 0; d4 < 16; d4++) {
                const float4 qd = qv4[d4];
                const float4 ka = k0[d4];
                const float4 kb = k1[d4];
                a0 += qd.x * ka.x + qd.y * ka.y + qd.z * ka.z + qd.w * ka.w;
                a1 += qd.x * kb.x + qd.y * kb.y + qd.z * kb.z + qd.w * kb.w;
            }
            a0 *= 0.125f; a1 *= 0.125f;

            float m = fmaxf(a0, a1);
            #pragma unroll
            for (int off = 16; off; off >>= 1)
                m = fmaxf(m, __shfl_xor_sync(0xffffffffu, m, off));
            const float e0 = __expf(a0 - m), e1 = __expf(a1 - m);
            float s = e0 + e1;
            #pragma unroll
            for (int off = 16; off; off >>= 1)
                s += __shfl_xor_sync(0xffffffffu, s, off);
            const float inv = 1.0f / s;
            const float p0 = e0 * inv, p1 = e1 * inv;

            float o0 = 0.f, o1 = 0.f;
            const float* v0 = Vs + (di * 32) * KROW;
            const float* v1 = Vs + (128 + dj * 32) * KROW;
            #pragma unroll
            for (int t = 0; t < 32; t++) {
                const float pt = __shfl_sync(0xffffffffu, p0, t);
                o0 += pt * v0[t * KROW + lane];
                o1 += pt * v0[t * KROW + lane + 32];
            }
            #pragma unroll
            for (int t = 0; t < 32; t++) {
                const float pt = __shfl_sync(0xffffffffu, p1, t);
                o0 += pt * v1[t * KROW + lane];
                o1 += pt * v1[t * KROW + lane + 32];
            }

            // fused [hi|lo|hi] split write
            const int n = (p << 10) + (i0 + di) * 32 + (j0 + dj);
            const size_t ab = (size_t)(b * NN + n) * KK + h * DD;
            const __nv_bfloat16 h0 = __float2bfloat16(o0);
            const __nv_bfloat16 l0 = __float2bfloat16(o0 - __bfloat162float(h0));
            const __nv_bfloat16 h1 = __float2bfloat16(o1);
            const __nv_bfloat16 l1 = __float2bfloat16(o1 - __bfloat162float(h1));
            Aout[ab + lane]             = h0;
            Aout[ab + 512 + lane]       = l0;
            Aout[ab + 1024 + lane]      = h0;
            Aout[ab + lane + 32]        = h1;
            Aout[ab + 512 + lane + 32]  = l1;
            Aout[ab + 1024 + lane + 32] = h1;
        }
    }
}

// ---------------------------------------------------------------------------
// Host side
// ---------------------------------------------------------------------------
extern "C" void kernel_launch(void* const* d_in, const int* in_sizes, int n_in,
                              void* d_out, int out_size)
{
    const float* x  = (const float*)d_in[0];
    const float* Wq = (const float*)d_in[1];
    const float* Wk = (const float*)d_in[2];
    const float* Wv = (const float*)d_in[3];
    const float* Wp = (const float*)d_in[4];
    const float* bp = (const float*)d_in[5];
    float* out = (float*)d_out;

    __nv_bfloat16 *A, *Bq, *Bo;
    float *qkv;
    cudaGetSymbolAddress((void**)&A,   g_A);
    cudaGetSymbolAddress((void**)&Bq,  g_Bqkv);
    cudaGetSymbolAddress((void**)&Bo,  g_Bout);
    cudaGetSymbolAddress((void**)&qkv, g_qkv);

    constexpr int SMEM_G = STAGES * STAGEB;                        // 81920
    constexpr int SMEM_A = (16 * QROW + 2 * 256 * KROW) * 4;       // 172544
    static bool s_attr = false;
    if (!s_attr) {
        cudaFuncSetAttribute(gemm_hmma,  cudaFuncAttributeMaxDynamicSharedMemorySize, SMEM_G);
        cudaFuncSetAttribute(attn_tile,  cudaFuncAttributeMaxDynamicSharedMemorySize, SMEM_A);
        s_attr = true;
    }

    // 1) hi/lo splits
    split3_a<<<(MM * 128 + 255) / 256, 256>>>(x, A, MM);
    split3_w<<<(CC * 128 + 255) / 256, 256>>>(Wq, Bq,                     CC);
    split3_w<<<(CC * 128 + 255) / 256, 256>>>(Wk, Bq + (size_t)512 * KK,  CC);
    split3_w<<<(CC * 128 + 255) / 256, 256>>>(Wv, Bq + (size_t)1024 * KK, CC);
    split3_w<<<(CC * 128 + 255) / 256, 256>>>(Wp, Bo,                     CC);

    // 2) fused QKV projection
    gemm_hmma<<<dim3(NQKV / 128, MM / 128), 256, SMEM_G>>>(A, Bq, qkv, NQKV, nullptr);

    // 3) tiled sparse attention (writes split A directly)
    attn_tile<<<NB * 3 * 64, 256, SMEM_A>>>(qkv, A);

    // 4) output projection with bias
    gemm_hmma<<<dim3(CC / 128, MM / 128), 256, SMEM_G>>>(A, Bo, out, CC, bp);
}